// round 1
// baseline (speedup 1.0000x reference)
#include <cuda_runtime.h>
#include <cstddef>

#define NN 100000
#define NE 3200000
#define NG 128
#define HD 64
#define BN_EPS 1e-5f

// ---------------- scratch (static device globals; no allocation) ----------------
__device__ __align__(16) float g_deg[NN];            // degree, then 1/max(deg,1)
__device__ __align__(16) float g_agg4[NN * 4];
__device__ __align__(16) float g_aggA[(size_t)NN * HD];
__device__ __align__(16) float g_aggB[(size_t)NN * HD];
__device__ __align__(16) float g_hA[(size_t)NN * HD];   // layer1 pre-BN
__device__ __align__(16) float g_hB[(size_t)NN * HD];   // layer2 pre-BN
__device__ __align__(16) float g_hC[(size_t)NN * HD];   // layer3 pre-BN
__device__ __align__(16) float g_bnsum[3 * HD];
__device__ __align__(16) float g_bnsq[3 * HD];
__device__ __align__(16) float g_scale[3 * HD];
__device__ __align__(16) float g_shift[3 * HD];
__device__ __align__(16) float g_pool[NG * HD];
__device__ __align__(16) float g_cnt[NG];

// ---------------- helpers ----------------
__device__ __forceinline__ void red_add(float* p, float v) {
    asm volatile("red.global.add.f32 [%0], %1;" :: "l"(p), "f"(v) : "memory");
}
__device__ __forceinline__ void red_add4(float* p, float4 v) {
    asm volatile("red.global.add.v4.f32 [%0], {%1, %2, %3, %4};"
                 :: "l"(p), "f"(v.x), "f"(v.y), "f"(v.z), "f"(v.w) : "memory");
}

// ---------------- zero all scratch ----------------
__global__ void zero_all_kernel() {
    size_t stride = (size_t)gridDim.x * blockDim.x;
    for (size_t j = (size_t)blockIdx.x * blockDim.x + threadIdx.x;
         j < (size_t)NN * HD; j += stride) {
        g_aggA[j] = 0.f;
        g_aggB[j] = 0.f;
        if (j < (size_t)NN * 4) g_agg4[j] = 0.f;
        if (j < NN) g_deg[j] = 0.f;
        if (j < NG * HD) g_pool[j] = 0.f;
        if (j < 3 * HD) { g_bnsum[j] = 0.f; g_bnsq[j] = 0.f; }
        if (j < NG) g_cnt[j] = 0.f;
    }
}

// ---------------- degree ----------------
__global__ void deg_kernel(const int* __restrict__ dst) {
    int e = blockIdx.x * blockDim.x + threadIdx.x;
    if (e < NE) red_add(&g_deg[dst[e]], 1.0f);
}
__global__ void deginv_kernel() {
    int i = blockIdx.x * blockDim.x + threadIdx.x;
    if (i < NN) g_deg[i] = 1.0f / fmaxf(g_deg[i], 1.0f);
}

// ---------------- layer-1 scatter (4-dim) ----------------
__global__ void scatter1_kernel(const int* __restrict__ src, const int* __restrict__ dst,
                                const float* __restrict__ x) {
    int e = blockIdx.x * blockDim.x + threadIdx.x;
    if (e >= NE) return;
    int s = src[e], d = dst[e];
    float4 v = __ldg((const float4*)(x + 4 * (size_t)s));
    red_add4(&g_agg4[4 * (size_t)d], v);
}

// ---------------- layer-1 node transform + BN stats ----------------
__global__ void node1_kernel(const float* __restrict__ x, const float* __restrict__ wl,
                             const float* __restrict__ b, const float* __restrict__ wr) {
    __shared__ float wls[HD * 4], wrs[HD * 4], bs[HD];
    int tid = threadIdx.x;
    if (tid < HD * 4) { wls[tid] = wl[tid]; wrs[tid] = wr[tid]; }
    if (tid < HD) bs[tid] = b[tid];
    __syncthreads();

    int n = blockIdx.x * blockDim.x + tid;
    bool act = n < NN;
    float di = act ? g_deg[n] : 0.f;
    float4 a = act ? *(const float4*)(g_agg4 + 4 * (size_t)n) : make_float4(0, 0, 0, 0);
    a.x *= di; a.y *= di; a.z *= di; a.w *= di;
    float4 xv = act ? __ldg((const float4*)(x + 4 * (size_t)n)) : make_float4(0, 0, 0, 0);
    int lane = tid & 31;

#pragma unroll
    for (int fb = 0; fb < 16; fb++) {
        float o[4];
#pragma unroll
        for (int j = 0; j < 4; j++) {
            int f = fb * 4 + j;
            float acc = bs[f];
            acc = fmaf(a.x, wls[f * 4 + 0], acc);
            acc = fmaf(a.y, wls[f * 4 + 1], acc);
            acc = fmaf(a.z, wls[f * 4 + 2], acc);
            acc = fmaf(a.w, wls[f * 4 + 3], acc);
            acc = fmaf(xv.x, wrs[f * 4 + 0], acc);
            acc = fmaf(xv.y, wrs[f * 4 + 1], acc);
            acc = fmaf(xv.z, wrs[f * 4 + 2], acc);
            acc = fmaf(xv.w, wrs[f * 4 + 3], acc);
            o[j] = acc;
        }
        if (act) *(float4*)(g_hA + (size_t)n * HD + fb * 4) = make_float4(o[0], o[1], o[2], o[3]);
#pragma unroll
        for (int j = 0; j < 4; j++) {
            float h = act ? o[j] : 0.f;
            float s = h, q = h * h;
#pragma unroll
            for (int off = 16; off; off >>= 1) {
                s += __shfl_xor_sync(0xffffffffu, s, off);
                q += __shfl_xor_sync(0xffffffffu, q, off);
            }
            if (lane == 0) {
                red_add(&g_bnsum[fb * 4 + j], s);
                red_add(&g_bnsq[fb * 4 + j], q);
            }
        }
    }
}

// ---------------- BN finalize: scale/shift ----------------
__global__ void bnfin_kernel(int idx, const float* __restrict__ gamma,
                             const float* __restrict__ beta) {
    int i = threadIdx.x;
    if (i >= HD) return;
    const float invn = 1.0f / (float)NN;
    float m = g_bnsum[idx * HD + i] * invn;
    float v = g_bnsq[idx * HD + i] * invn - m * m;
    float s = gamma[i] * rsqrtf(v + BN_EPS);
    g_scale[idx * HD + i] = s;
    g_shift[idx * HD + i] = beta[i] - m * s;
}

// ---------------- 64-wide scatter with fused BN-affine + ReLU on source ----------------
__global__ void scatter64_kernel(const int* __restrict__ src, const int* __restrict__ dst,
                                 int aff, int which) {
    const float* __restrict__ hin = (which == 0) ? g_hA : g_hB;
    float* __restrict__ agg = (which == 0) ? g_aggA : g_aggB;
    long long t = (long long)blockIdx.x * blockDim.x + threadIdx.x;
    int e = (int)(t >> 4);
    if (e >= NE) return;
    int c = ((int)t & 15) * 4;
    int s = src[e], d = dst[e];
    float4 v = __ldg((const float4*)(hin + (size_t)s * HD + c));
    float4 sc = *(const float4*)(g_scale + aff * HD + c);
    float4 sh = *(const float4*)(g_shift + aff * HD + c);
    v.x = fmaxf(fmaf(v.x, sc.x, sh.x), 0.f);
    v.y = fmaxf(fmaf(v.y, sc.y, sh.y), 0.f);
    v.z = fmaxf(fmaf(v.z, sc.z, sh.z), 0.f);
    v.w = fmaxf(fmaf(v.w, sc.w, sh.w), 0.f);
    red_add4(agg + (size_t)d * HD + c, v);
}

// ---------------- layer 2/3 node transform (smem GEMM) + BN stats ----------------
// 128 threads, 64 nodes/block. Two phases: (Wl, agg*deg_inv) then (Wr, bn_relu(h_prev)).
__global__ void node64_kernel(int aff, const float* __restrict__ wl,
                              const float* __restrict__ bias, const float* __restrict__ wr,
                              int which, int stat) {
    const float* __restrict__ agg = (which == 0) ? g_aggA : g_aggB;
    const float* __restrict__ hin = (which == 0) ? g_hA : g_hB;
    float* __restrict__ hout = (which == 0) ? g_hB : g_hC;

    __shared__ __align__(16) float in_s[64 * 69];
    __shared__ __align__(16) float W_s[64 * 68];

    int tid = threadIdx.x;
    int base = blockIdx.x * 64;
    int tx = tid & 7, ty = tid >> 3;
    int f0 = tx * 8, n0 = ty * 4;

    float acc[4][8];
#pragma unroll
    for (int i = 0; i < 4; i++)
#pragma unroll
        for (int j = 0; j < 8; j++) acc[i][j] = 0.f;

    for (int phase = 0; phase < 2; phase++) {
        const float* __restrict__ W = phase ? wr : wl;
        for (int i = tid; i < 64 * 16; i += 128) {
            int f = i >> 4, kc = (i & 15) * 4;
            float4 a = __ldg((const float4*)(W + f * 64 + kc));
            W_s[(kc + 0) * 68 + f] = a.x;
            W_s[(kc + 1) * 68 + f] = a.y;
            W_s[(kc + 2) * 68 + f] = a.z;
            W_s[(kc + 3) * 68 + f] = a.w;
        }
        for (int i = tid; i < 64 * 16; i += 128) {
            int n = i >> 4, kc = (i & 15) * 4;
            int gn = base + n;
            float4 v = make_float4(0, 0, 0, 0);
            if (gn < NN) {
                if (phase == 0) {
                    float di = g_deg[gn];
                    v = __ldg((const float4*)(agg + (size_t)gn * HD + kc));
                    v.x *= di; v.y *= di; v.z *= di; v.w *= di;
                } else {
                    v = __ldg((const float4*)(hin + (size_t)gn * HD + kc));
                    float4 sc = *(const float4*)(g_scale + aff * HD + kc);
                    float4 sh = *(const float4*)(g_shift + aff * HD + kc);
                    v.x = fmaxf(fmaf(v.x, sc.x, sh.x), 0.f);
                    v.y = fmaxf(fmaf(v.y, sc.y, sh.y), 0.f);
                    v.z = fmaxf(fmaf(v.z, sc.z, sh.z), 0.f);
                    v.w = fmaxf(fmaf(v.w, sc.w, sh.w), 0.f);
                }
            }
            in_s[n * 69 + kc + 0] = v.x;
            in_s[n * 69 + kc + 1] = v.y;
            in_s[n * 69 + kc + 2] = v.z;
            in_s[n * 69 + kc + 3] = v.w;
        }
        __syncthreads();
#pragma unroll 8
        for (int k = 0; k < 64; k++) {
            float4 w0 = *(const float4*)&W_s[k * 68 + f0];
            float4 w1 = *(const float4*)&W_s[k * 68 + f0 + 4];
#pragma unroll
            for (int i = 0; i < 4; i++) {
                float a = in_s[(n0 + i) * 69 + k];
                acc[i][0] = fmaf(a, w0.x, acc[i][0]);
                acc[i][1] = fmaf(a, w0.y, acc[i][1]);
                acc[i][2] = fmaf(a, w0.z, acc[i][2]);
                acc[i][3] = fmaf(a, w0.w, acc[i][3]);
                acc[i][4] = fmaf(a, w1.x, acc[i][4]);
                acc[i][5] = fmaf(a, w1.y, acc[i][5]);
                acc[i][6] = fmaf(a, w1.z, acc[i][6]);
                acc[i][7] = fmaf(a, w1.w, acc[i][7]);
            }
        }
        __syncthreads();
    }

    // epilogue: bias, store, BN partial sums
    float bsv[8];
#pragma unroll
    for (int j = 0; j < 8; j++) bsv[j] = __ldg(bias + f0 + j);

    float psum[8], psq[8];
#pragma unroll
    for (int j = 0; j < 8; j++) { psum[j] = 0.f; psq[j] = 0.f; }

#pragma unroll
    for (int i = 0; i < 4; i++) {
        int gn = base + n0 + i;
        if (gn < NN) {
            float h[8];
#pragma unroll
            for (int j = 0; j < 8; j++) {
                h[j] = acc[i][j] + bsv[j];
                psum[j] += h[j];
                psq[j] += h[j] * h[j];
            }
            *(float4*)(hout + (size_t)gn * HD + f0) = make_float4(h[0], h[1], h[2], h[3]);
            *(float4*)(hout + (size_t)gn * HD + f0 + 4) = make_float4(h[4], h[5], h[6], h[7]);
        }
    }
#pragma unroll
    for (int j = 0; j < 8; j++) {
        float s = psum[j], q = psq[j];
        s += __shfl_xor_sync(0xffffffffu, s, 8);
        q += __shfl_xor_sync(0xffffffffu, q, 8);
        s += __shfl_xor_sync(0xffffffffu, s, 16);
        q += __shfl_xor_sync(0xffffffffu, q, 16);
        if (((tid & 31) >> 3) == 0) {
            red_add(&g_bnsum[stat * HD + f0 + j], s);
            red_add(&g_bnsq[stat * HD + f0 + j], q);
        }
    }
}

// ---------------- mean-pool over graphs (fused BN-affine + ReLU of layer 3) ----------------
__global__ void pool_kernel(const int* __restrict__ batch) {
    long long t = (long long)blockIdx.x * blockDim.x + threadIdx.x;
    int n = (int)(t >> 4);
    if (n >= NN) return;
    int c = ((int)t & 15) * 4;
    int b = batch[n];
    float4 v = __ldg((const float4*)(g_hC + (size_t)n * HD + c));
    float4 sc = *(const float4*)(g_scale + 2 * HD + c);
    float4 sh = *(const float4*)(g_shift + 2 * HD + c);
    v.x = fmaxf(fmaf(v.x, sc.x, sh.x), 0.f);
    v.y = fmaxf(fmaf(v.y, sc.y, sh.y), 0.f);
    v.z = fmaxf(fmaf(v.z, sc.z, sh.z), 0.f);
    v.w = fmaxf(fmaf(v.w, sc.w, sh.w), 0.f);
    red_add4(&g_pool[b * HD + c], v);
    if (c == 0) red_add(&g_cnt[b], 1.0f);
}

// ---------------- MLP head ----------------
__global__ void head_kernel(const float* __restrict__ fc1w, const float* __restrict__ fc1b,
                            const float* __restrict__ fc2w, const float* __restrict__ fc2b,
                            float* __restrict__ out) {
    __shared__ float w1s[64 * 64];
    int tid = threadIdx.x;  // 128
    for (int i = tid; i < 64 * 64; i += 128) w1s[i] = fc1w[i];
    __syncthreads();
    if (tid < NG) {
        float ci = 1.0f / fmaxf(g_cnt[tid], 1.0f);
        float p[64];
#pragma unroll
        for (int f = 0; f < 64; f++) p[f] = g_pool[tid * HD + f] * ci;
        float hid[64];
#pragma unroll
        for (int j = 0; j < 64; j++) {
            float acc = fc1b[j];
#pragma unroll
            for (int f = 0; f < 64; f++) acc = fmaf(p[f], w1s[j * 64 + f], acc);
            hid[j] = fmaxf(acc, 0.f);
        }
#pragma unroll
        for (int u = 0; u < 2; u++) {
            float acc = fc2b[u];
#pragma unroll
            for (int j = 0; j < 64; j++) acc = fmaf(hid[j], __ldg(fc2w + u * 64 + j), acc);
            out[tid * 2 + u] = acc;
        }
    }
}

// ---------------- launch ----------------
extern "C" void kernel_launch(void* const* d_in, const int* in_sizes, int n_in,
                              void* d_out, int out_size) {
    const float* x    = (const float*)d_in[0];
    const int*   ei   = (const int*)d_in[1];
    const int*   src  = ei;
    const int*   dst  = ei + NE;
    const int*   bat  = (const int*)d_in[2];
    const float* w1l  = (const float*)d_in[3];
    const float* b1   = (const float*)d_in[4];
    const float* w1r  = (const float*)d_in[5];
    const float* g1   = (const float*)d_in[6];
    const float* be1  = (const float*)d_in[7];
    const float* w2l  = (const float*)d_in[8];
    const float* b2   = (const float*)d_in[9];
    const float* w2r  = (const float*)d_in[10];
    const float* g2   = (const float*)d_in[11];
    const float* be2  = (const float*)d_in[12];
    const float* w3l  = (const float*)d_in[13];
    const float* b3   = (const float*)d_in[14];
    const float* w3r  = (const float*)d_in[15];
    const float* g3   = (const float*)d_in[16];
    const float* be3  = (const float*)d_in[17];
    const float* fc1w = (const float*)d_in[18];
    const float* fc1b = (const float*)d_in[19];
    const float* fc2w = (const float*)d_in[20];
    const float* fc2b = (const float*)d_in[21];
    float* out = (float*)d_out;

    zero_all_kernel<<<8192, 256>>>();
    deg_kernel<<<(NE + 255) / 256, 256>>>(dst);
    deginv_kernel<<<(NN + 255) / 256, 256>>>();

    // layer 1
    scatter1_kernel<<<(NE + 255) / 256, 256>>>(src, dst, x);
    node1_kernel<<<(NN + 255) / 256, 256>>>(x, w1l, b1, w1r);
    bnfin_kernel<<<1, 64>>>(0, g1, be1);

    // layer 2
    scatter64_kernel<<<(int)(((long long)NE * 16 + 255) / 256), 256>>>(src, dst, 0, 0);
    node64_kernel<<<(NN + 63) / 64, 128>>>(0, w2l, b2, w2r, 0, 1);
    bnfin_kernel<<<1, 64>>>(1, g2, be2);

    // layer 3
    scatter64_kernel<<<(int)(((long long)NE * 16 + 255) / 256), 256>>>(src, dst, 1, 1);
    node64_kernel<<<(NN + 63) / 64, 128>>>(1, w3l, b3, w3r, 1, 2);
    bnfin_kernel<<<1, 64>>>(2, g3, be3);

    // pool + head
    pool_kernel<<<(int)(((long long)NN * 16 + 255) / 256), 256>>>(bat);
    head_kernel<<<1, 128>>>(fc1w, fc1b, fc2w, fc2b, out);
}

// round 3
// speedup vs baseline: 1.1798x; 1.1798x over previous
#include <cuda_runtime.h>
#include <cstddef>

#define NN 100000
#define NE 3200000
#define NG 128
#define HD 64
#define BN_EPS 1e-5f
#define SCAN_BLK 1024
#define NBLK ((NN + SCAN_BLK - 1) / SCAN_BLK)

// ---------------- scratch (static device globals; no allocation) ----------------
__device__ __align__(16) int   g_count[NN];
__device__ __align__(16) int   g_rowptr[NN + 1];
__device__ __align__(16) int   g_cursor[NN];
__device__ __align__(16) int   g_bsum[NBLK];
__device__ __align__(16) int   g_csr[NE];
__device__ __align__(16) float g_deg[NN];            // 1/max(deg,1)
__device__ __align__(16) float g_agg4[NN * 4];
__device__ __align__(16) float g_aggA[(size_t)NN * HD];
__device__ __align__(16) float g_hA[(size_t)NN * HD];   // layer1 pre-BN
__device__ __align__(16) float g_hB[(size_t)NN * HD];   // layer2 pre-BN
__device__ __align__(16) float g_hC[(size_t)NN * HD];   // layer3 pre-BN
__device__ __align__(16) float g_bnsum[3 * HD];
__device__ __align__(16) float g_bnsq[3 * HD];
__device__ __align__(16) float g_scale[3 * HD];
__device__ __align__(16) float g_shift[3 * HD];
__device__ __align__(16) float g_pool[NG * HD];
__device__ __align__(16) float g_cnt[NG];

// ---------------- helpers ----------------
__device__ __forceinline__ void red_add(float* p, float v) {
    asm volatile("red.global.add.f32 [%0], %1;" :: "l"(p), "f"(v) : "memory");
}
__device__ __forceinline__ void red_add4(float* p, float4 v) {
    asm volatile("red.global.add.v4.f32 [%0], {%1, %2, %3, %4};"
                 :: "l"(p), "f"(v.x), "f"(v.y), "f"(v.z), "f"(v.w) : "memory");
}

// ---------------- zero the small scratch ----------------
__global__ void zero_small_kernel() {
    int i = blockIdx.x * blockDim.x + threadIdx.x;
    if (i < NN) g_count[i] = 0;
    if (i < NG * HD) g_pool[i] = 0.f;
    if (i < 3 * HD) { g_bnsum[i] = 0.f; g_bnsq[i] = 0.f; }
    if (i < NG) g_cnt[i] = 0.f;
}

// ---------------- CSR build: histogram ----------------
__global__ void hist_kernel(const int* __restrict__ dst) {
    int e = blockIdx.x * blockDim.x + threadIdx.x;
    if (e < NE) atomicAdd(&g_count[dst[e]], 1);
}

// ---------------- CSR build: block-level exclusive scan ----------------
__global__ void scan1_kernel() {
    int i = blockIdx.x * SCAN_BLK + threadIdx.x;
    int lane = threadIdx.x & 31, wid = threadIdx.x >> 5;
    int v = (i < NN) ? g_count[i] : 0;
    int inc = v;
#pragma unroll
    for (int o = 1; o < 32; o <<= 1) {
        int t = __shfl_up_sync(0xffffffffu, inc, o);
        if (lane >= o) inc += t;
    }
    __shared__ int wsum[32];
    if (lane == 31) wsum[wid] = inc;
    __syncthreads();
    if (wid == 0) {
        int t = wsum[lane];
        int ti = t;
#pragma unroll
        for (int o = 1; o < 32; o <<= 1) {
            int u = __shfl_up_sync(0xffffffffu, ti, o);
            if (lane >= o) ti += u;
        }
        wsum[lane] = ti - t;   // exclusive warp offsets
    }
    __syncthreads();
    int excl = inc - v + wsum[wid];
    if (i < NN) g_rowptr[i] = excl;
    if (threadIdx.x == SCAN_BLK - 1) g_bsum[blockIdx.x] = excl + v;
}

__global__ void scan2_kernel() {
    if (threadIdx.x == 0) {
        int acc = 0;
        for (int i = 0; i < NBLK; i++) { int t = g_bsum[i]; g_bsum[i] = acc; acc += t; }
    }
}

__global__ void scan3_kernel() {
    int i = blockIdx.x * SCAN_BLK + threadIdx.x;
    if (i < NN) {
        int rp = g_rowptr[i] + g_bsum[blockIdx.x];
        g_rowptr[i] = rp;
        g_cursor[i] = rp;
        g_deg[i] = 1.0f / fmaxf((float)g_count[i], 1.0f);
    }
    if (i == 0) g_rowptr[NN] = NE;
}

// ---------------- CSR build: placement ----------------
__global__ void place_kernel(const int* __restrict__ src, const int* __restrict__ dst) {
    int e = blockIdx.x * blockDim.x + threadIdx.x;
    if (e >= NE) return;
    int pos = atomicAdd(&g_cursor[dst[e]], 1);
    g_csr[pos] = src[e];
}

// ---------------- layer-1 gather (4-dim): warp per node ----------------
__global__ void gather1_kernel(const float* __restrict__ x) {
    int wi = (blockIdx.x * blockDim.x + threadIdx.x) >> 5;
    if (wi >= NN) return;
    int lane = threadIdx.x & 31;
    int beg = g_rowptr[wi], end = g_rowptr[wi + 1];
    float4 acc = make_float4(0.f, 0.f, 0.f, 0.f);
    for (int i = beg + lane; i < end; i += 32) {
        int s = g_csr[i];
        float4 v = __ldg((const float4*)(x + 4 * (size_t)s));
        acc.x += v.x; acc.y += v.y; acc.z += v.z; acc.w += v.w;
    }
#pragma unroll
    for (int o = 16; o; o >>= 1) {
        acc.x += __shfl_xor_sync(0xffffffffu, acc.x, o);
        acc.y += __shfl_xor_sync(0xffffffffu, acc.y, o);
        acc.z += __shfl_xor_sync(0xffffffffu, acc.z, o);
        acc.w += __shfl_xor_sync(0xffffffffu, acc.w, o);
    }
    if (lane == 0) *(float4*)(g_agg4 + 4 * (size_t)wi) = acc;
}

// ---------------- layer-1 node transform + BN stats ----------------
__global__ void node1_kernel(const float* __restrict__ x, const float* __restrict__ wl,
                             const float* __restrict__ b, const float* __restrict__ wr) {
    __shared__ float wls[HD * 4], wrs[HD * 4], bs[HD];
    int tid = threadIdx.x;
    if (tid < HD * 4) { wls[tid] = wl[tid]; wrs[tid] = wr[tid]; }
    if (tid < HD) bs[tid] = b[tid];
    __syncthreads();

    int n = blockIdx.x * blockDim.x + tid;
    bool act = n < NN;
    float di = act ? g_deg[n] : 0.f;
    float4 a = act ? *(const float4*)(g_agg4 + 4 * (size_t)n) : make_float4(0, 0, 0, 0);
    a.x *= di; a.y *= di; a.z *= di; a.w *= di;
    float4 xv = act ? __ldg((const float4*)(x + 4 * (size_t)n)) : make_float4(0, 0, 0, 0);
    int lane = tid & 31;

#pragma unroll
    for (int fb = 0; fb < 16; fb++) {
        float o[4];
#pragma unroll
        for (int j = 0; j < 4; j++) {
            int f = fb * 4 + j;
            float acc = bs[f];
            acc = fmaf(a.x, wls[f * 4 + 0], acc);
            acc = fmaf(a.y, wls[f * 4 + 1], acc);
            acc = fmaf(a.z, wls[f * 4 + 2], acc);
            acc = fmaf(a.w, wls[f * 4 + 3], acc);
            acc = fmaf(xv.x, wrs[f * 4 + 0], acc);
            acc = fmaf(xv.y, wrs[f * 4 + 1], acc);
            acc = fmaf(xv.z, wrs[f * 4 + 2], acc);
            acc = fmaf(xv.w, wrs[f * 4 + 3], acc);
            o[j] = acc;
        }
        if (act) *(float4*)(g_hA + (size_t)n * HD + fb * 4) = make_float4(o[0], o[1], o[2], o[3]);
#pragma unroll
        for (int j = 0; j < 4; j++) {
            float h = act ? o[j] : 0.f;
            float s = h, q = h * h;
#pragma unroll
            for (int off = 16; off; off >>= 1) {
                s += __shfl_xor_sync(0xffffffffu, s, off);
                q += __shfl_xor_sync(0xffffffffu, q, off);
            }
            if (lane == 0) {
                red_add(&g_bnsum[fb * 4 + j], s);
                red_add(&g_bnsq[fb * 4 + j], q);
            }
        }
    }
}

// ---------------- BN finalize: scale/shift ----------------
__global__ void bnfin_kernel(int idx, const float* __restrict__ gamma,
                             const float* __restrict__ beta) {
    int i = threadIdx.x;
    if (i >= HD) return;
    const float invn = 1.0f / (float)NN;
    float m = g_bnsum[idx * HD + i] * invn;
    float v = g_bnsq[idx * HD + i] * invn - m * m;
    float s = gamma[i] * rsqrtf(v + BN_EPS);
    g_scale[idx * HD + i] = s;
    g_shift[idx * HD + i] = beta[i] - m * s;
}

// ---------------- 64-wide gather with fused BN-affine + ReLU on source ----------------
// One warp per destination node. Lane l owns columns l and l+32.
__global__ void gather64_kernel(int aff, int which) {
    const float* __restrict__ hin = (which == 0) ? g_hA : g_hB;
    int wi = (blockIdx.x * blockDim.x + threadIdx.x) >> 5;
    if (wi >= NN) return;
    int lane = threadIdx.x & 31;
    float sc0 = g_scale[aff * HD + lane],      sh0 = g_shift[aff * HD + lane];
    float sc1 = g_scale[aff * HD + 32 + lane], sh1 = g_shift[aff * HD + 32 + lane];
    int beg = g_rowptr[wi], end = g_rowptr[wi + 1];
    float a0 = 0.f, a1 = 0.f;
    for (int base = beg; base < end; base += 32) {
        int idx = base + lane;
        int sv = (idx < end) ? g_csr[idx] : 0;
        int m = end - base;
        if (m > 32) m = 32;
        int j = 0;
        for (; j + 4 <= m; j += 4) {
            int s0 = __shfl_sync(0xffffffffu, sv, j + 0);
            int s1 = __shfl_sync(0xffffffffu, sv, j + 1);
            int s2 = __shfl_sync(0xffffffffu, sv, j + 2);
            int s3 = __shfl_sync(0xffffffffu, sv, j + 3);
            float x00 = __ldg(hin + (size_t)s0 * HD + lane);
            float x01 = __ldg(hin + (size_t)s0 * HD + 32 + lane);
            float x10 = __ldg(hin + (size_t)s1 * HD + lane);
            float x11 = __ldg(hin + (size_t)s1 * HD + 32 + lane);
            float x20 = __ldg(hin + (size_t)s2 * HD + lane);
            float x21 = __ldg(hin + (size_t)s2 * HD + 32 + lane);
            float x30 = __ldg(hin + (size_t)s3 * HD + lane);
            float x31 = __ldg(hin + (size_t)s3 * HD + 32 + lane);
            a0 += fmaxf(fmaf(x00, sc0, sh0), 0.f);
            a1 += fmaxf(fmaf(x01, sc1, sh1), 0.f);
            a0 += fmaxf(fmaf(x10, sc0, sh0), 0.f);
            a1 += fmaxf(fmaf(x11, sc1, sh1), 0.f);
            a0 += fmaxf(fmaf(x20, sc0, sh0), 0.f);
            a1 += fmaxf(fmaf(x21, sc1, sh1), 0.f);
            a0 += fmaxf(fmaf(x30, sc0, sh0), 0.f);
            a1 += fmaxf(fmaf(x31, sc1, sh1), 0.f);
        }
        for (; j < m; j++) {
            int s = __shfl_sync(0xffffffffu, sv, j);
            float x0 = __ldg(hin + (size_t)s * HD + lane);
            float x1 = __ldg(hin + (size_t)s * HD + 32 + lane);
            a0 += fmaxf(fmaf(x0, sc0, sh0), 0.f);
            a1 += fmaxf(fmaf(x1, sc1, sh1), 0.f);
        }
    }
    g_aggA[(size_t)wi * HD + lane] = a0;
    g_aggA[(size_t)wi * HD + 32 + lane] = a1;
}

// ---------------- layer 2/3 node transform (smem GEMM) + BN stats ----------------
// 128 threads, 64 nodes/block. Two phases: (Wl, agg*deg_inv) then (Wr, bn_relu(h_prev)).
__global__ void node64_kernel(int aff, const float* __restrict__ wl,
                              const float* __restrict__ bias, const float* __restrict__ wr,
                              int which, int stat) {
    const float* __restrict__ hin = (which == 0) ? g_hA : g_hB;
    float* __restrict__ hout = (which == 0) ? g_hB : g_hC;

    __shared__ __align__(16) float in_s[64 * 69];
    __shared__ __align__(16) float W_s[64 * 68];

    int tid = threadIdx.x;
    int base = blockIdx.x * 64;
    int tx = tid & 7, ty = tid >> 3;
    int f0 = tx * 8, n0 = ty * 4;

    float acc[4][8];
#pragma unroll
    for (int i = 0; i < 4; i++)
#pragma unroll
        for (int j = 0; j < 8; j++) acc[i][j] = 0.f;

    for (int phase = 0; phase < 2; phase++) {
        const float* __restrict__ W = phase ? wr : wl;
        for (int i = tid; i < 64 * 16; i += 128) {
            int f = i >> 4, kc = (i & 15) * 4;
            float4 a = __ldg((const float4*)(W + f * 64 + kc));
            W_s[(kc + 0) * 68 + f] = a.x;
            W_s[(kc + 1) * 68 + f] = a.y;
            W_s[(kc + 2) * 68 + f] = a.z;
            W_s[(kc + 3) * 68 + f] = a.w;
        }
        for (int i = tid; i < 64 * 16; i += 128) {
            int n = i >> 4, kc = (i & 15) * 4;
            int gn = base + n;
            float4 v = make_float4(0, 0, 0, 0);
            if (gn < NN) {
                if (phase == 0) {
                    float di = g_deg[gn];
                    v = __ldg((const float4*)(g_aggA + (size_t)gn * HD + kc));
                    v.x *= di; v.y *= di; v.z *= di; v.w *= di;
                } else {
                    v = __ldg((const float4*)(hin + (size_t)gn * HD + kc));
                    float4 sc = *(const float4*)(g_scale + aff * HD + kc);
                    float4 sh = *(const float4*)(g_shift + aff * HD + kc);
                    v.x = fmaxf(fmaf(v.x, sc.x, sh.x), 0.f);
                    v.y = fmaxf(fmaf(v.y, sc.y, sh.y), 0.f);
                    v.z = fmaxf(fmaf(v.z, sc.z, sh.z), 0.f);
                    v.w = fmaxf(fmaf(v.w, sc.w, sh.w), 0.f);
                }
            }
            in_s[n * 69 + kc + 0] = v.x;
            in_s[n * 69 + kc + 1] = v.y;
            in_s[n * 69 + kc + 2] = v.z;
            in_s[n * 69 + kc + 3] = v.w;
        }
        __syncthreads();
#pragma unroll 8
        for (int k = 0; k < 64; k++) {
            float4 w0 = *(const float4*)&W_s[k * 68 + f0];
            float4 w1 = *(const float4*)&W_s[k * 68 + f0 + 4];
#pragma unroll
            for (int i = 0; i < 4; i++) {
                float a = in_s[(n0 + i) * 69 + k];
                acc[i][0] = fmaf(a, w0.x, acc[i][0]);
                acc[i][1] = fmaf(a, w0.y, acc[i][1]);
                acc[i][2] = fmaf(a, w0.z, acc[i][2]);
                acc[i][3] = fmaf(a, w0.w, acc[i][3]);
                acc[i][4] = fmaf(a, w1.x, acc[i][4]);
                acc[i][5] = fmaf(a, w1.y, acc[i][5]);
                acc[i][6] = fmaf(a, w1.z, acc[i][6]);
                acc[i][7] = fmaf(a, w1.w, acc[i][7]);
            }
        }
        __syncthreads();
    }

    // epilogue: bias, store, BN partial sums
    float bsv[8];
#pragma unroll
    for (int j = 0; j < 8; j++) bsv[j] = __ldg(bias + f0 + j);

    float psum[8], psq[8];
#pragma unroll
    for (int j = 0; j < 8; j++) { psum[j] = 0.f; psq[j] = 0.f; }

#pragma unroll
    for (int i = 0; i < 4; i++) {
        int gn = base + n0 + i;
        if (gn < NN) {
            float h[8];
#pragma unroll
            for (int j = 0; j < 8; j++) {
                h[j] = acc[i][j] + bsv[j];
                psum[j] += h[j];
                psq[j] += h[j] * h[j];
            }
            *(float4*)(hout + (size_t)gn * HD + f0) = make_float4(h[0], h[1], h[2], h[3]);
            *(float4*)(hout + (size_t)gn * HD + f0 + 4) = make_float4(h[4], h[5], h[6], h[7]);
        }
    }
#pragma unroll
    for (int j = 0; j < 8; j++) {
        float s = psum[j], q = psq[j];
        s += __shfl_xor_sync(0xffffffffu, s, 8);
        q += __shfl_xor_sync(0xffffffffu, q, 8);
        s += __shfl_xor_sync(0xffffffffu, s, 16);
        q += __shfl_xor_sync(0xffffffffu, q, 16);
        if (((tid & 31) >> 3) == 0) {
            red_add(&g_bnsum[stat * HD + f0 + j], s);
            red_add(&g_bnsq[stat * HD + f0 + j], q);
        }
    }
}

// ---------------- mean-pool over graphs (fused BN-affine + ReLU of layer 3) ----------------
__global__ void pool_kernel(const int* __restrict__ batch) {
    long long t = (long long)blockIdx.x * blockDim.x + threadIdx.x;
    int n = (int)(t >> 4);
    if (n >= NN) return;
    int c = ((int)t & 15) * 4;
    int b = batch[n];
    float4 v = __ldg((const float4*)(g_hC + (size_t)n * HD + c));
    float4 sc = *(const float4*)(g_scale + 2 * HD + c);
    float4 sh = *(const float4*)(g_shift + 2 * HD + c);
    v.x = fmaxf(fmaf(v.x, sc.x, sh.x), 0.f);
    v.y = fmaxf(fmaf(v.y, sc.y, sh.y), 0.f);
    v.z = fmaxf(fmaf(v.z, sc.z, sh.z), 0.f);
    v.w = fmaxf(fmaf(v.w, sc.w, sh.w), 0.f);
    red_add4(&g_pool[b * HD + c], v);
    if (c == 0) red_add(&g_cnt[b], 1.0f);
}

// ---------------- MLP head ----------------
__global__ void head_kernel(const float* __restrict__ fc1w, const float* __restrict__ fc1b,
                            const float* __restrict__ fc2w, const float* __restrict__ fc2b,
                            float* __restrict__ out) {
    __shared__ float w1s[64 * 64];
    int tid = threadIdx.x;  // 128
    for (int i = tid; i < 64 * 64; i += 128) w1s[i] = fc1w[i];
    __syncthreads();
    if (tid < NG) {
        float ci = 1.0f / fmaxf(g_cnt[tid], 1.0f);
        float p[64];
#pragma unroll
        for (int f = 0; f < 64; f++) p[f] = g_pool[tid * HD + f] * ci;
        float hid[64];
#pragma unroll
        for (int j = 0; j < 64; j++) {
            float acc = fc1b[j];
#pragma unroll
            for (int f = 0; f < 64; f++) acc = fmaf(p[f], w1s[j * 64 + f], acc);
            hid[j] = fmaxf(acc, 0.f);
        }
#pragma unroll
        for (int u = 0; u < 2; u++) {
            float acc = fc2b[u];
#pragma unroll
            for (int j = 0; j < 64; j++) acc = fmaf(hid[j], __ldg(fc2w + u * 64 + j), acc);
            out[tid * 2 + u] = acc;
        }
    }
}

// ---------------- launch ----------------
extern "C" void kernel_launch(void* const* d_in, const int* in_sizes, int n_in,
                              void* d_out, int out_size) {
    const float* x    = (const float*)d_in[0];
    const int*   ei   = (const int*)d_in[1];
    const int*   src  = ei;
    const int*   dst  = ei + NE;
    const int*   bat  = (const int*)d_in[2];
    const float* w1l  = (const float*)d_in[3];
    const float* b1   = (const float*)d_in[4];
    const float* w1r  = (const float*)d_in[5];
    const float* g1   = (const float*)d_in[6];
    const float* be1  = (const float*)d_in[7];
    const float* w2l  = (const float*)d_in[8];
    const float* b2   = (const float*)d_in[9];
    const float* w2r  = (const float*)d_in[10];
    const float* g2   = (const float*)d_in[11];
    const float* be2  = (const float*)d_in[12];
    const float* w3l  = (const float*)d_in[13];
    const float* b3   = (const float*)d_in[14];
    const float* w3r  = (const float*)d_in[15];
    const float* g3   = (const float*)d_in[16];
    const float* be3  = (const float*)d_in[17];
    const float* fc1w = (const float*)d_in[18];
    const float* fc1b = (const float*)d_in[19];
    const float* fc2w = (const float*)d_in[20];
    const float* fc2b = (const float*)d_in[21];
    float* out = (float*)d_out;

    // small scratch zeroing + CSR build
    zero_small_kernel<<<(NN + 255) / 256, 256>>>();
    hist_kernel<<<(NE + 255) / 256, 256>>>(dst);
    scan1_kernel<<<NBLK, SCAN_BLK>>>();
    scan2_kernel<<<1, 32>>>();
    scan3_kernel<<<NBLK, SCAN_BLK>>>();
    place_kernel<<<(NE + 255) / 256, 256>>>(src, dst);

    // layer 1
    gather1_kernel<<<(NN * 32 + 255) / 256, 256>>>(x);
    node1_kernel<<<(NN + 255) / 256, 256>>>(x, w1l, b1, w1r);
    bnfin_kernel<<<1, 64>>>(0, g1, be1);

    // layer 2
    gather64_kernel<<<(NN * 32 + 255) / 256, 256>>>(0, 0);
    node64_kernel<<<(NN + 63) / 64, 128>>>(0, w2l, b2, w2r, 0, 1);
    bnfin_kernel<<<1, 64>>>(1, g2, be2);

    // layer 3
    gather64_kernel<<<(NN * 32 + 255) / 256, 256>>>(1, 1);
    node64_kernel<<<(NN + 63) / 64, 128>>>(1, w3l, b3, w3r, 1, 2);
    bnfin_kernel<<<1, 64>>>(2, g3, be3);

    // pool + head
    pool_kernel<<<(int)(((long long)NN * 16 + 255) / 256), 256>>>(bat);
    head_kernel<<<1, 128>>>(fc1w, fc1b, fc2w, fc2b, out);
}

// round 5
// speedup vs baseline: 1.2743x; 1.0802x over previous
#include <cuda_runtime.h>
#include <cuda_fp16.h>
#include <cstddef>

#define NN 100000
#define NE 3200000
#define NG 128
#define HD 64
#define BN_EPS 1e-5f
#define SCAN_BLK 1024
#define NBLK ((NN + SCAN_BLK - 1) / SCAN_BLK)

// ---------------- scratch (static device globals; no allocation) ----------------
__device__ __align__(16) int   g_count[NN];
__device__ __align__(16) int   g_rowptr[NN + 1];
__device__ __align__(16) int   g_cursor[NN];
__device__ __align__(16) int   g_bsum[NBLK];
__device__ __align__(16) int   g_csr[NE];
__device__ __align__(16) float g_deg[NN];            // 1/max(deg,1)
__device__ __align__(16) float g_agg4[NN * 4];
__device__ __align__(16) float g_aggA[(size_t)NN * HD];
__device__ __align__(16) float g_hA[(size_t)NN * HD];   // layer1 pre-BN
__device__ __align__(16) float g_hB[(size_t)NN * HD];   // layer2 pre-BN
__device__ __align__(16) float g_hC[(size_t)NN * HD];   // layer3 pre-BN
__device__ __align__(16) __half g_h16A[(size_t)NN * HD]; // relu(bn1(hA)) fp16
__device__ __align__(16) __half g_h16B[(size_t)NN * HD]; // relu(bn2(hB)) fp16
__device__ __align__(16) __half g_h16C[(size_t)NN * HD]; // relu(bn3(hC)) fp16
__device__ __align__(16) float g_bnsum[3 * HD];
__device__ __align__(16) float g_bnsq[3 * HD];
__device__ __align__(16) float g_scale[3 * HD];
__device__ __align__(16) float g_shift[3 * HD];
__device__ __align__(16) float g_pool[NG * HD];
__device__ __align__(16) float g_cnt[NG];

// ---------------- helpers ----------------
__device__ __forceinline__ void red_add(float* p, float v) {
    asm volatile("red.global.add.f32 [%0], %1;" :: "l"(p), "f"(v) : "memory");
}

// ---------------- zero the small scratch ----------------
__global__ void zero_small_kernel() {
    int i = blockIdx.x * blockDim.x + threadIdx.x;
    if (i < NN) g_count[i] = 0;
    if (i < NG * HD) g_pool[i] = 0.f;
    if (i < 3 * HD) { g_bnsum[i] = 0.f; g_bnsq[i] = 0.f; }
    if (i < NG) g_cnt[i] = 0.f;
}

// ---------------- CSR build: histogram ----------------
__global__ void hist_kernel(const int* __restrict__ dst) {
    int e = blockIdx.x * blockDim.x + threadIdx.x;
    if (e < NE) atomicAdd(&g_count[dst[e]], 1);
}

// ---------------- CSR build: block-level exclusive scan ----------------
__global__ void scan1_kernel() {
    int i = blockIdx.x * SCAN_BLK + threadIdx.x;
    int lane = threadIdx.x & 31, wid = threadIdx.x >> 5;
    int v = (i < NN) ? g_count[i] : 0;
    int inc = v;
#pragma unroll
    for (int o = 1; o < 32; o <<= 1) {
        int t = __shfl_up_sync(0xffffffffu, inc, o);
        if (lane >= o) inc += t;
    }
    __shared__ int wsum[32];
    if (lane == 31) wsum[wid] = inc;
    __syncthreads();
    if (wid == 0) {
        int t = wsum[lane];
        int ti = t;
#pragma unroll
        for (int o = 1; o < 32; o <<= 1) {
            int u = __shfl_up_sync(0xffffffffu, ti, o);
            if (lane >= o) ti += u;
        }
        wsum[lane] = ti - t;   // exclusive warp offsets
    }
    __syncthreads();
    int excl = inc - v + wsum[wid];
    if (i < NN) g_rowptr[i] = excl;
    if (threadIdx.x == SCAN_BLK - 1) g_bsum[blockIdx.x] = excl + v;
}

__global__ void scan2_kernel() {
    if (threadIdx.x == 0) {
        int acc = 0;
        for (int i = 0; i < NBLK; i++) { int t = g_bsum[i]; g_bsum[i] = acc; acc += t; }
    }
}

__global__ void scan3_kernel() {
    int i = blockIdx.x * SCAN_BLK + threadIdx.x;
    if (i < NN) {
        int rp = g_rowptr[i] + g_bsum[blockIdx.x];
        g_rowptr[i] = rp;
        g_cursor[i] = rp;
        g_deg[i] = 1.0f / fmaxf((float)g_count[i], 1.0f);
    }
    if (i == 0) g_rowptr[NN] = NE;
}

// ---------------- CSR build: placement ----------------
__global__ void place_kernel(const int* __restrict__ src, const int* __restrict__ dst) {
    int e = blockIdx.x * blockDim.x + threadIdx.x;
    if (e >= NE) return;
    int pos = atomicAdd(&g_cursor[dst[e]], 1);
    g_csr[pos] = src[e];
}

// ---------------- layer-1 gather (4-dim): warp per node ----------------
__global__ void gather1_kernel(const float* __restrict__ x) {
    int wi = (blockIdx.x * blockDim.x + threadIdx.x) >> 5;
    if (wi >= NN) return;
    int lane = threadIdx.x & 31;
    int beg = g_rowptr[wi], end = g_rowptr[wi + 1];
    float4 acc = make_float4(0.f, 0.f, 0.f, 0.f);
    for (int i = beg + lane; i < end; i += 32) {
        int s = g_csr[i];
        float4 v = __ldg((const float4*)(x + 4 * (size_t)s));
        acc.x += v.x; acc.y += v.y; acc.z += v.z; acc.w += v.w;
    }
#pragma unroll
    for (int o = 16; o; o >>= 1) {
        acc.x += __shfl_xor_sync(0xffffffffu, acc.x, o);
        acc.y += __shfl_xor_sync(0xffffffffu, acc.y, o);
        acc.z += __shfl_xor_sync(0xffffffffu, acc.z, o);
        acc.w += __shfl_xor_sync(0xffffffffu, acc.w, o);
    }
    if (lane == 0) *(float4*)(g_agg4 + 4 * (size_t)wi) = acc;
}

// ---------------- layer-1 node transform + BN stats ----------------
__global__ void node1_kernel(const float* __restrict__ x, const float* __restrict__ wl,
                             const float* __restrict__ b, const float* __restrict__ wr) {
    __shared__ float wls[HD * 4], wrs[HD * 4], bs[HD];
    int tid = threadIdx.x;
    if (tid < HD * 4) { wls[tid] = wl[tid]; wrs[tid] = wr[tid]; }
    if (tid < HD) bs[tid] = b[tid];
    __syncthreads();

    int n = blockIdx.x * blockDim.x + tid;
    bool act = n < NN;
    float di = act ? g_deg[n] : 0.f;
    float4 a = act ? *(const float4*)(g_agg4 + 4 * (size_t)n) : make_float4(0, 0, 0, 0);
    a.x *= di; a.y *= di; a.z *= di; a.w *= di;
    float4 xv = act ? __ldg((const float4*)(x + 4 * (size_t)n)) : make_float4(0, 0, 0, 0);
    int lane = tid & 31;

#pragma unroll
    for (int fb = 0; fb < 16; fb++) {
        float o[4];
#pragma unroll
        for (int j = 0; j < 4; j++) {
            int f = fb * 4 + j;
            float acc = bs[f];
            acc = fmaf(a.x, wls[f * 4 + 0], acc);
            acc = fmaf(a.y, wls[f * 4 + 1], acc);
            acc = fmaf(a.z, wls[f * 4 + 2], acc);
            acc = fmaf(a.w, wls[f * 4 + 3], acc);
            acc = fmaf(xv.x, wrs[f * 4 + 0], acc);
            acc = fmaf(xv.y, wrs[f * 4 + 1], acc);
            acc = fmaf(xv.z, wrs[f * 4 + 2], acc);
            acc = fmaf(xv.w, wrs[f * 4 + 3], acc);
            o[j] = acc;
        }
        if (act) *(float4*)(g_hA + (size_t)n * HD + fb * 4) = make_float4(o[0], o[1], o[2], o[3]);
#pragma unroll
        for (int j = 0; j < 4; j++) {
            float h = act ? o[j] : 0.f;
            float s = h, q = h * h;
#pragma unroll
            for (int off = 16; off; off >>= 1) {
                s += __shfl_xor_sync(0xffffffffu, s, off);
                q += __shfl_xor_sync(0xffffffffu, q, off);
            }
            if (lane == 0) {
                red_add(&g_bnsum[fb * 4 + j], s);
                red_add(&g_bnsq[fb * 4 + j], q);
            }
        }
    }
}

// ---------------- BN finalize: scale/shift ----------------
__global__ void bnfin_kernel(int idx, const float* __restrict__ gamma,
                             const float* __restrict__ beta) {
    int i = threadIdx.x;
    if (i >= HD) return;
    const float invn = 1.0f / (float)NN;
    float m = g_bnsum[idx * HD + i] * invn;
    float v = g_bnsq[idx * HD + i] * invn - m * m;
    float s = gamma[i] * rsqrtf(v + BN_EPS);
    g_scale[idx * HD + i] = s;
    g_shift[idx * HD + i] = beta[i] - m * s;
}

// ---------------- convert: h_pre -> fp16 relu(bn(h)) ----------------
// which: 0 -> hA->h16A (aff 0), 1 -> hB->h16B (aff 1), 2 -> hC->h16C (aff 2).
__global__ void cvt_kernel(int which) {
    const float* __restrict__ hin = (which == 0) ? g_hA : (which == 1) ? g_hB : g_hC;
    __half* __restrict__ hout = (which == 0) ? g_h16A : (which == 1) ? g_h16B : g_h16C;
    int aff = which;
    int t = blockIdx.x * blockDim.x + threadIdx.x;
    if (t >= NN * 8) return;
    int n = t >> 3, c = (t & 7) * 8;
    float4 v0 = __ldg((const float4*)(hin + (size_t)n * HD + c));
    float4 v1 = __ldg((const float4*)(hin + (size_t)n * HD + c + 4));
    float4 sc0 = *(const float4*)(g_scale + aff * HD + c);
    float4 sh0 = *(const float4*)(g_shift + aff * HD + c);
    float4 sc1 = *(const float4*)(g_scale + aff * HD + c + 4);
    float4 sh1 = *(const float4*)(g_shift + aff * HD + c + 4);
    float r0 = fmaxf(fmaf(v0.x, sc0.x, sh0.x), 0.f);
    float r1 = fmaxf(fmaf(v0.y, sc0.y, sh0.y), 0.f);
    float r2 = fmaxf(fmaf(v0.z, sc0.z, sh0.z), 0.f);
    float r3 = fmaxf(fmaf(v0.w, sc0.w, sh0.w), 0.f);
    float r4 = fmaxf(fmaf(v1.x, sc1.x, sh1.x), 0.f);
    float r5 = fmaxf(fmaf(v1.y, sc1.y, sh1.y), 0.f);
    float r6 = fmaxf(fmaf(v1.z, sc1.z, sh1.z), 0.f);
    float r7 = fmaxf(fmaf(v1.w, sc1.w, sh1.w), 0.f);
    __half2 h0 = __floats2half2_rn(r0, r1);
    __half2 h1 = __floats2half2_rn(r2, r3);
    __half2 h2 = __floats2half2_rn(r4, r5);
    __half2 h3 = __floats2half2_rn(r6, r7);
    __half2* dst = (__half2*)(hout + (size_t)n * HD + c);
    dst[0] = h0; dst[1] = h1; dst[2] = h2; dst[3] = h3;
}

// ---------------- 64-wide gather over fp16 features ----------------
// One warp per destination node. Lane l owns columns 2l, 2l+1 (one half2 = 4B,
// warp reads exactly one 128B line per edge). which: 0 -> h16A, 1 -> h16B.
__global__ void gather64_kernel(int which) {
    const __half2* __restrict__ hin = (const __half2*)((which == 0) ? g_h16A : g_h16B);
    int wi = (blockIdx.x * blockDim.x + threadIdx.x) >> 5;
    if (wi >= NN) return;
    int lane = threadIdx.x & 31;
    int beg = g_rowptr[wi], end = g_rowptr[wi + 1];
    float a0 = 0.f, a1 = 0.f;
    for (int base = beg; base < end; base += 32) {
        int idx = base + lane;
        int sv = (idx < end) ? g_csr[idx] : 0;
        int m = end - base;
        if (m > 32) m = 32;
        int j = 0;
        for (; j + 4 <= m; j += 4) {
            int s0 = __shfl_sync(0xffffffffu, sv, j + 0);
            int s1 = __shfl_sync(0xffffffffu, sv, j + 1);
            int s2 = __shfl_sync(0xffffffffu, sv, j + 2);
            int s3 = __shfl_sync(0xffffffffu, sv, j + 3);
            __half2 v0 = __ldg(hin + (size_t)s0 * 32 + lane);
            __half2 v1 = __ldg(hin + (size_t)s1 * 32 + lane);
            __half2 v2 = __ldg(hin + (size_t)s2 * 32 + lane);
            __half2 v3 = __ldg(hin + (size_t)s3 * 32 + lane);
            float2 f0 = __half22float2(v0);
            float2 f1 = __half22float2(v1);
            float2 f2 = __half22float2(v2);
            float2 f3 = __half22float2(v3);
            a0 += f0.x + f1.x; a1 += f0.y + f1.y;
            a0 += f2.x + f3.x; a1 += f2.y + f3.y;
        }
        for (; j < m; j++) {
            int s = __shfl_sync(0xffffffffu, sv, j);
            float2 f = __half22float2(__ldg(hin + (size_t)s * 32 + lane));
            a0 += f.x; a1 += f.y;
        }
    }
    *(float2*)(g_aggA + (size_t)wi * HD + 2 * lane) = make_float2(a0, a1);
}

// ---------------- layer 2/3 node transform (smem GEMM) + BN stats ----------------
// 128 threads, 64 nodes/block. Phase 0: (Wl, agg*deg_inv); phase 1: (Wr, h16 prev).
// which: 0 -> in h16A, out hB, stat 1;  1 -> in h16B, out hC, stat 2.
__global__ void node64_kernel(int which, const float* __restrict__ wl,
                              const float* __restrict__ bias, const float* __restrict__ wr) {
    const __half2* __restrict__ h16in = (const __half2*)((which == 0) ? g_h16A : g_h16B);
    float* __restrict__ hout = (which == 0) ? g_hB : g_hC;
    int stat = which + 1;

    __shared__ __align__(16) float in_s[64 * 69];
    __shared__ __align__(16) float W_s[64 * 68];

    int tid = threadIdx.x;
    int base = blockIdx.x * 64;
    int tx = tid & 7, ty = tid >> 3;
    int f0 = tx * 8, n0 = ty * 4;

    float acc[4][8];
#pragma unroll
    for (int i = 0; i < 4; i++)
#pragma unroll
        for (int j = 0; j < 8; j++) acc[i][j] = 0.f;

    for (int phase = 0; phase < 2; phase++) {
        const float* __restrict__ W = phase ? wr : wl;
        for (int i = tid; i < 64 * 16; i += 128) {
            int f = i >> 4, kc = (i & 15) * 4;
            float4 a = __ldg((const float4*)(W + f * 64 + kc));
            W_s[(kc + 0) * 68 + f] = a.x;
            W_s[(kc + 1) * 68 + f] = a.y;
            W_s[(kc + 2) * 68 + f] = a.z;
            W_s[(kc + 3) * 68 + f] = a.w;
        }
        if (phase == 0) {
            for (int i = tid; i < 64 * 16; i += 128) {
                int n = i >> 4, kc = (i & 15) * 4;
                int gn = base + n;
                float4 v = make_float4(0, 0, 0, 0);
                if (gn < NN) {
                    float di = g_deg[gn];
                    v = __ldg((const float4*)(g_aggA + (size_t)gn * HD + kc));
                    v.x *= di; v.y *= di; v.z *= di; v.w *= di;
                }
                in_s[n * 69 + kc + 0] = v.x;
                in_s[n * 69 + kc + 1] = v.y;
                in_s[n * 69 + kc + 2] = v.z;
                in_s[n * 69 + kc + 3] = v.w;
            }
        } else {
            for (int i = tid; i < 64 * 16; i += 128) {
                int n = i >> 4, cp = (i & 15) * 2;   // half2 pair index
                int gn = base + n;
                float2 f0v = make_float2(0.f, 0.f), f1v = make_float2(0.f, 0.f);
                if (gn < NN) {
                    f0v = __half22float2(__ldg(h16in + (size_t)gn * 32 + cp));
                    f1v = __half22float2(__ldg(h16in + (size_t)gn * 32 + cp + 1));
                }
                in_s[n * 69 + 2 * cp + 0] = f0v.x;
                in_s[n * 69 + 2 * cp + 1] = f0v.y;
                in_s[n * 69 + 2 * cp + 2] = f1v.x;
                in_s[n * 69 + 2 * cp + 3] = f1v.y;
            }
        }
        __syncthreads();
#pragma unroll 8
        for (int k = 0; k < 64; k++) {
            float4 w0 = *(const float4*)&W_s[k * 68 + f0];
            float4 w1 = *(const float4*)&W_s[k * 68 + f0 + 4];
#pragma unroll
            for (int i = 0; i < 4; i++) {
                float a = in_s[(n0 + i) * 69 + k];
                acc[i][0] = fmaf(a, w0.x, acc[i][0]);
                acc[i][1] = fmaf(a, w0.y, acc[i][1]);
                acc[i][2] = fmaf(a, w0.z, acc[i][2]);
                acc[i][3] = fmaf(a, w0.w, acc[i][3]);
                acc[i][4] = fmaf(a, w1.x, acc[i][4]);
                acc[i][5] = fmaf(a, w1.y, acc[i][5]);
                acc[i][6] = fmaf(a, w1.z, acc[i][6]);
                acc[i][7] = fmaf(a, w1.w, acc[i][7]);
            }
        }
        __syncthreads();
    }

    // epilogue: bias, store, BN partial sums
    float bsv[8];
#pragma unroll
    for (int j = 0; j < 8; j++) bsv[j] = __ldg(bias + f0 + j);

    float psum[8], psq[8];
#pragma unroll
    for (int j = 0; j < 8; j++) { psum[j] = 0.f; psq[j] = 0.f; }

#pragma unroll
    for (int i = 0; i < 4; i++) {
        int gn = base + n0 + i;
        if (gn < NN) {
            float h[8];
#pragma unroll
            for (int j = 0; j < 8; j++) {
                h[j] = acc[i][j] + bsv[j];
                psum[j] += h[j];
                psq[j] += h[j] * h[j];
            }
            *(float4*)(hout + (size_t)gn * HD + f0) = make_float4(h[0], h[1], h[2], h[3]);
            *(float4*)(hout + (size_t)gn * HD + f0 + 4) = make_float4(h[4], h[5], h[6], h[7]);
        }
    }
#pragma unroll
    for (int j = 0; j < 8; j++) {
        float s = psum[j], q = psq[j];
        s += __shfl_xor_sync(0xffffffffu, s, 8);
        q += __shfl_xor_sync(0xffffffffu, q, 8);
        s += __shfl_xor_sync(0xffffffffu, s, 16);
        q += __shfl_xor_sync(0xffffffffu, q, 16);
        if (((tid & 31) >> 3) == 0) {
            red_add(&g_bnsum[stat * HD + f0 + j], s);
            red_add(&g_bnsq[stat * HD + f0 + j], q);
        }
    }
}

// ---------------- mean-pool over graphs (sorted batch -> run-flush) ----------------
// One warp per 32 consecutive nodes; lane l owns cols 2l,2l+1. Atomics only at
// graph-boundary flushes (batch_ids are sorted).
__global__ void pool_kernel(const int* __restrict__ batch) {
    const __half2* __restrict__ h16 = (const __half2*)g_h16C;
    int warp = (blockIdx.x * blockDim.x + threadIdx.x) >> 5;
    const int nwarps = NN / 32;  // 3125 (NN divisible by 32)
    if (warp >= nwarps) return;
    int lane = threadIdx.x & 31;
    int n0 = warp * 32, n1 = n0 + 32;
    int cur = __ldg(batch + n0);
    int runStart = n0;
    float a0 = 0.f, a1 = 0.f;
    for (int n = n0; n < n1; n++) {
        int b = __ldg(batch + n);
        if (b != cur) {
            red_add(&g_pool[cur * HD + 2 * lane], a0);
            red_add(&g_pool[cur * HD + 2 * lane + 1], a1);
            if (lane == 0) red_add(&g_cnt[cur], (float)(n - runStart));
            cur = b; runStart = n; a0 = 0.f; a1 = 0.f;
        }
        float2 f = __half22float2(__ldg(h16 + (size_t)n * 32 + lane));
        a0 += f.x; a1 += f.y;
    }
    red_add(&g_pool[cur * HD + 2 * lane], a0);
    red_add(&g_pool[cur * HD + 2 * lane + 1], a1);
    if (lane == 0) red_add(&g_cnt[cur], (float)(n1 - runStart));
}

// ---------------- MLP head ----------------
__global__ void head_kernel(const float* __restrict__ fc1w, const float* __restrict__ fc1b,
                            const float* __restrict__ fc2w, const float* __restrict__ fc2b,
                            float* __restrict__ out) {
    __shared__ float w1s[64 * 64];
    int tid = threadIdx.x;  // 128
    for (int i = tid; i < 64 * 64; i += 128) w1s[i] = fc1w[i];
    __syncthreads();
    if (tid < NG) {
        float ci = 1.0f / fmaxf(g_cnt[tid], 1.0f);
        float p[64];
#pragma unroll
        for (int f = 0; f < 64; f++) p[f] = g_pool[tid * HD + f] * ci;
        float hid[64];
#pragma unroll
        for (int j = 0; j < 64; j++) {
            float acc = fc1b[j];
#pragma unroll
            for (int f = 0; f < 64; f++) acc = fmaf(p[f], w1s[j * 64 + f], acc);
            hid[j] = fmaxf(acc, 0.f);
        }
#pragma unroll
        for (int u = 0; u < 2; u++) {
            float acc = fc2b[u];
#pragma unroll
            for (int j = 0; j < 64; j++) acc = fmaf(hid[j], __ldg(fc2w + u * 64 + j), acc);
            out[tid * 2 + u] = acc;
        }
    }
}

// ---------------- launch ----------------
extern "C" void kernel_launch(void* const* d_in, const int* in_sizes, int n_in,
                              void* d_out, int out_size) {
    const float* x    = (const float*)d_in[0];
    const int*   ei   = (const int*)d_in[1];
    const int*   src  = ei;
    const int*   dst  = ei + NE;
    const int*   bat  = (const int*)d_in[2];
    const float* w1l  = (const float*)d_in[3];
    const float* b1   = (const float*)d_in[4];
    const float* w1r  = (const float*)d_in[5];
    const float* g1   = (const float*)d_in[6];
    const float* be1  = (const float*)d_in[7];
    const float* w2l  = (const float*)d_in[8];
    const float* b2   = (const float*)d_in[9];
    const float* w2r  = (const float*)d_in[10];
    const float* g2   = (const float*)d_in[11];
    const float* be2  = (const float*)d_in[12];
    const float* w3l  = (const float*)d_in[13];
    const float* b3   = (const float*)d_in[14];
    const float* w3r  = (const float*)d_in[15];
    const float* g3   = (const float*)d_in[16];
    const float* be3  = (const float*)d_in[17];
    const float* fc1w = (const float*)d_in[18];
    const float* fc1b = (const float*)d_in[19];
    const float* fc2w = (const float*)d_in[20];
    const float* fc2b = (const float*)d_in[21];
    float* out = (float*)d_out;

    // small scratch zeroing + CSR build
    zero_small_kernel<<<(NN + 255) / 256, 256>>>();
    hist_kernel<<<(NE + 255) / 256, 256>>>(dst);
    scan1_kernel<<<NBLK, SCAN_BLK>>>();
    scan2_kernel<<<1, 32>>>();
    scan3_kernel<<<NBLK, SCAN_BLK>>>();
    place_kernel<<<(NE + 255) / 256, 256>>>(src, dst);

    // layer 1
    gather1_kernel<<<(NN * 32 + 255) / 256, 256>>>(x);
    node1_kernel<<<(NN + 255) / 256, 256>>>(x, w1l, b1, w1r);
    bnfin_kernel<<<1, 64>>>(0, g1, be1);
    cvt_kernel<<<(NN * 8 + 255) / 256, 256>>>(0);

    // layer 2
    gather64_kernel<<<(NN * 32 + 255) / 256, 256>>>(0);
    node64_kernel<<<(NN + 63) / 64, 128>>>(0, w2l, b2, w2r);
    bnfin_kernel<<<1, 64>>>(1, g2, be2);
    cvt_kernel<<<(NN * 8 + 255) / 256, 256>>>(1);

    // layer 3
    gather64_kernel<<<(NN * 32 + 255) / 256, 256>>>(1);
    node64_kernel<<<(NN + 63) / 64, 128>>>(1, w3l, b3, w3r);
    bnfin_kernel<<<1, 64>>>(2, g3, be3);
    cvt_kernel<<<(NN * 8 + 255) / 256, 256>>>(2);

    // pool + head
    pool_kernel<<<(NN + 255) / 256, 256>>>(bat);
    head_kernel<<<1, 128>>>(fc1w, fc1b, fc2w, fc2b, out);
}